// round 15
// baseline (speedup 1.0000x reference)
#include <cuda_runtime.h>
#include <cstdint>

#define B_ 256
#define T_ 512
#define C_ 256
#define L_ 64

__device__ float g_loss[B_];
__device__ unsigned int g_ctr = 0;

#define BAR_SYNC(ID)   asm volatile("bar.sync %0, 288;"   :: "n"(ID) : "memory")
#define BAR_ARRIVE(ID) asm volatile("bar.arrive %0, 288;" :: "n"(ID) : "memory")

// ---------------------------------------------------------------------------
// Fused CTC kernel: one block per batch row, warp-specialized, 16-row phases
// (32 phases instead of 64 -> half the barrier/sync/drain overhead).
//   warps 0-7 (producers): TWO rows per phase (rows 16p+w and 16p+8+w), the
//     two softmaxes interleaved for ILP (independent exp/shfl-reduce chains),
//     2-phase register lookahead, write [eb*256 | p_odd*mask*256] rows into a
//     4-slot x 16-row ring.
//   warp 8 (consumer): CTC recurrence (4 states/lane + s=128 on lane 31,
//     1 shfl/step, 2^8 pre-scale, pipelined power-of-2 renorm every 8 steps).
// Batch mean folded in via atomic ticket (replay-safe reset).
// ---------------------------------------------------------------------------
__global__ void __launch_bounds__(288) ctc_fused_kernel(
    const float* __restrict__ logits,
    const int* __restrict__ targets,
    const int* __restrict__ input_lengths,
    const int* __restrict__ target_lengths,
    float* __restrict__ out) {
  __shared__ float ring[4][16][68];    // [slot][time-row][state], 17.4 KB
  __shared__ float scratch[8][2][C_];  // per-producer-warp, per-row exp scratch
  __shared__ int   stg[L_];
  __shared__ float shf[132];

  int b = blockIdx.x;
  int tid = threadIdx.x;
  int wid = tid >> 5, lane = tid & 31;
  int len = input_lengths[b];
  int tl  = target_lengths[b];
  int Sb  = 2 * tl + 1;

  if (tid < L_) stg[tid] = targets[b * L_ + tid];
  __syncthreads();

  const float* lg = logits + (size_t)b * T_ * C_;

  if (wid < 8) {
    // ---------------- producers (2 rows/phase) ----------------
    int t0l = stg[2 * lane], t1l = stg[2 * lane + 1];
    float m1 = (4 * lane + 1 < Sb) ? 1.f : 0.f;
    float m3 = (4 * lane + 3 < Sb) ? 1.f : 0.f;
    float* scr0 = scratch[wid][0];
    float* scr1 = scratch[wid][1];

#define LOADPH(PH, R0A, R0B, R1A, R1B)                                     \
    do {                                                                   \
      int rA_ = (PH) * 16 + wid;     rA_ = rA_ < T_ ? rA_ : T_ - 1;        \
      int rB_ = (PH) * 16 + 8 + wid; rB_ = rB_ < T_ ? rB_ : T_ - 1;        \
      const float4* pA_ = (const float4*)(lg + (size_t)rA_ * C_);          \
      const float4* pB_ = (const float4*)(lg + (size_t)rB_ * C_);          \
      (R0A) = pA_[lane]; (R0B) = pA_[lane + 32];                           \
      (R1A) = pB_[lane]; (R1B) = pB_[lane + 32];                           \
    } while (0)

#define PRODUCE2(V0A, V0B, V1A, V1B, SLOT)                                 \
    do {                                                                   \
      float4 e0A, e0B, e1A, e1B;                                           \
      e0A.x = __expf((V0A).x); e0A.y = __expf((V0A).y);                    \
      e0A.z = __expf((V0A).z); e0A.w = __expf((V0A).w);                    \
      e1A.x = __expf((V1A).x); e1A.y = __expf((V1A).y);                    \
      e1A.z = __expf((V1A).z); e1A.w = __expf((V1A).w);                    \
      e0B.x = __expf((V0B).x); e0B.y = __expf((V0B).y);                    \
      e0B.z = __expf((V0B).z); e0B.w = __expf((V0B).w);                    \
      e1B.x = __expf((V1B).x); e1B.y = __expf((V1B).y);                    \
      e1B.z = __expf((V1B).z); e1B.w = __expf((V1B).w);                    \
      float s0 = ((e0A.x + e0A.y) + (e0A.z + e0A.w)) +                     \
                 ((e0B.x + e0B.y) + (e0B.z + e0B.w));                      \
      float s1 = ((e1A.x + e1A.y) + (e1A.z + e1A.w)) +                     \
                 ((e1B.x + e1B.y) + (e1B.z + e1B.w));                      \
      _Pragma("unroll")                                                    \
      for (int o = 16; o; o >>= 1) {                                       \
        s0 += __shfl_xor_sync(0xffffffffu, s0, o);                         \
        s1 += __shfl_xor_sync(0xffffffffu, s1, o);                         \
      }                                                                    \
      float i0 = __frcp_rn(s0) * 256.f;                                    \
      float i1 = __frcp_rn(s1) * 256.f;                                    \
      ((float4*)scr0)[lane]      = e0A;                                    \
      ((float4*)scr0)[lane + 32] = e0B;                                    \
      ((float4*)scr1)[lane]      = e1A;                                    \
      ((float4*)scr1)[lane + 32] = e1B;                                    \
      __syncwarp();                                                        \
      float* rw0 = ring[SLOT][wid];                                        \
      float* rw1 = ring[SLOT][wid + 8];                                    \
      float2 o0, o1;                                                       \
      o0.x = scr0[t0l] * i0 * m1;  o0.y = scr0[t1l] * i0 * m3;             \
      o1.x = scr1[t0l] * i1 * m1;  o1.y = scr1[t1l] * i1 * m3;             \
      ((float2*)(rw0 + 4))[lane] = o0;                                     \
      ((float2*)(rw1 + 4))[lane] = o1;                                     \
      if (lane == 0) { rw0[0] = scr0[0] * i0; rw1[0] = scr1[0] * i1; }     \
      __syncwarp();                                                        \
    } while (0)

    float4 aA, aB, aC, aD, cOA, cOB, cOC, cOD, cEA, cEB, cEC, cED;
    float4 nA, nB, nC, nD;
    // preamble: fill slots 0-3 (phases 0-3), staging 2 phases ahead
    LOADPH(0, aA, aB, aC, aD);
    LOADPH(1, cOA, cOB, cOC, cOD);
    LOADPH(2, cEA, cEB, cEC, cED);
    PRODUCE2(aA, aB, aC, aD, 0);                       BAR_ARRIVE(1);
    LOADPH(3, nA, nB, nC, nD);
    PRODUCE2(cOA, cOB, cOC, cOD, 1);
    cOA = nA; cOB = nB; cOC = nC; cOD = nD;            BAR_ARRIVE(2);
    LOADPH(4, nA, nB, nC, nD);
    PRODUCE2(cEA, cEB, cEC, cED, 2);
    cEA = nA; cEB = nB; cEC = nC; cED = nD;            BAR_ARRIVE(3);
    LOADPH(5, nA, nB, nC, nD);
    PRODUCE2(cOA, cOB, cOC, cOD, 3);
    cOA = nA; cOB = nB; cOC = nC; cOD = nD;            BAR_ARRIVE(4);

    for (int p = 4; p < 32; p += 4) {
      LOADPH(p + 2, nA, nB, nC, nD); BAR_SYNC(5);
      PRODUCE2(cEA, cEB, cEC, cED, 0);
      cEA = nA; cEB = nB; cEC = nC; cED = nD;          BAR_ARRIVE(1);
      LOADPH(p + 3, nA, nB, nC, nD); BAR_SYNC(6);
      PRODUCE2(cOA, cOB, cOC, cOD, 1);
      cOA = nA; cOB = nB; cOC = nC; cOD = nD;          BAR_ARRIVE(2);
      LOADPH(p + 4, nA, nB, nC, nD); BAR_SYNC(7);
      PRODUCE2(cEA, cEB, cEC, cED, 2);
      cEA = nA; cEB = nB; cEC = nC; cED = nD;          BAR_ARRIVE(3);
      LOADPH(p + 5, nA, nB, nC, nD); BAR_SYNC(8);
      PRODUCE2(cOA, cOB, cOC, cOD, 3);
      cOA = nA; cOB = nB; cOC = nC; cOD = nD;          BAR_ARRIVE(4);
    }
#undef LOADPH
#undef PRODUCE2
  } else {
    // ---------------- consumer (warp 8) ----------------
    int t0l = stg[2 * lane], t1l = stg[2 * lane + 1];
    float skip1 = 0.f, skip3 = (t1l != t0l) ? 1.f : 0.f;
    if (lane > 0) skip1 = (t0l != stg[2 * lane - 1]) ? 1.f : 0.f;
    float c0 = (lane > 0 && 4 * lane < Sb) ? 1.f : 0.f;

    float a0 = 0.f, a1 = 0.f, a2 = 0.f, a3 = 0.f, a4 = 0.f;
    int e_total = 0, epend = 0;
    float fpend = 1.f;

#define CTC_STEP(EB, PL)                                                   \
    do {                                                                   \
      float u1 = __shfl_up_sync(0xffffffffu, a3, 1);                       \
      float n0 = fmaf(u1, c0, a0) * (EB);                                  \
      float n1 = fmaf(skip1, u1, a1 + a0) * (PL).x;                        \
      float n2 = (a2 + a1) * (EB);                                         \
      float n3 = fmaf(skip3, a1, a3 + a2) * (PL).y;                        \
      float n4 = (a4 + a3) * (EB);                                         \
      a0 = n0; a1 = n1; a2 = n2; a3 = n3; a4 = n4;                         \
    } while (0)

#define CTC_RENORM_PIPE()                                                  \
    do {                                                                   \
      a0 *= fpend; a1 *= fpend; a2 *= fpend; a3 *= fpend; a4 *= fpend;     \
      e_total += epend;                                                    \
      float lm = fmaxf(fmaxf(a0, a1), fmaxf(fmaxf(a2, a3), a4));           \
      unsigned mb = __reduce_max_sync(0xffffffffu, __float_as_uint(lm));   \
      epend = (mb != 0u) ? ((int)(mb >> 23) - 127) : 0;                    \
      fpend = __int_as_float((127 - epend) << 23);                         \
    } while (0)

#define CTC_PHASE(P, SLOT)                                                 \
    do {                                                                   \
      float(*buf)[68] = ring[(SLOT)];                                      \
      float  ebv[16];                                                      \
      float2 plv[16];                                                      \
      _Pragma("unroll")                                                    \
      for (int u = 0; u < 16; u++) {                                       \
        ebv[u] = buf[u][0];                                                \
        plv[u] = ((float2*)(buf[u] + 4))[lane];                            \
      }                                                                    \
      _Pragma("unroll")                                                    \
      for (int u = 0; u < 16; u++) {                                       \
        int tt = (P) * 16 + u;                                             \
        if (tt == 0) {                                                     \
          if (lane == 0) {                                                 \
            a0 = ebv[0] * (1.f / 256.f);                                   \
            a1 = plv[0].x * (1.f / 256.f);                                 \
          }                                                                \
        } else if (tt < len) {                                             \
          CTC_STEP(ebv[u], plv[u]);                                        \
          if ((tt & 7) == 7) CTC_RENORM_PIPE();                            \
        }                                                                  \
      }                                                                    \
    } while (0)

    for (int p = 0; p < 28; p += 4) {
      BAR_SYNC(1); CTC_PHASE(p + 0, 0); BAR_ARRIVE(5);
      BAR_SYNC(2); CTC_PHASE(p + 1, 1); BAR_ARRIVE(6);
      BAR_SYNC(3); CTC_PHASE(p + 2, 2); BAR_ARRIVE(7);
      BAR_SYNC(4); CTC_PHASE(p + 3, 3); BAR_ARRIVE(8);
    }
    BAR_SYNC(1); CTC_PHASE(28, 0);
    BAR_SYNC(2); CTC_PHASE(29, 1);
    BAR_SYNC(3); CTC_PHASE(30, 2);
    BAR_SYNC(4); CTC_PHASE(31, 3);

    // per-row loss
    shf[4 * lane + 0] = a0;
    shf[4 * lane + 1] = a1;
    shf[4 * lane + 2] = a2;
    shf[4 * lane + 3] = a3;
    if (lane == 31) shf[128] = a4;
    __syncwarp();
    if (lane == 0) {
      float ssum = shf[2 * tl] + shf[2 * tl - 1];
      // a_true = a_stored * 2^(e_total - 8*(len-1))
      float loss = -(logf(ssum) +
                     (float)(e_total - 8 * (len - 1)) * 0.69314718055994530942f);
      if (!isfinite(loss) || loss > 1e20f) loss = 0.f;   // zero_infinity
      g_loss[b] = loss / (float)tl;
    }

    // fold the batch mean into the last-arriving block (replay-safe)
    __threadfence();
    unsigned tkt = 0;
    if (lane == 0) tkt = atomicAdd(&g_ctr, 1u);
    tkt = __shfl_sync(0xffffffffu, tkt, 0);
    if (tkt == B_ - 1) {
      __threadfence();
      float v = 0.f;
      #pragma unroll
      for (int j = 0; j < 8; j++) v += __ldcg(&g_loss[lane * 8 + j]);
      #pragma unroll
      for (int o = 16; o; o >>= 1) v += __shfl_xor_sync(0xffffffffu, v, o);
      if (lane == 0) {
        *out = v * (1.0f / (float)B_);
        atomicExch(&g_ctr, 0u);                        // reset for graph replay
      }
    }
#undef CTC_STEP
#undef CTC_RENORM_PIPE
#undef CTC_PHASE
  }
}

extern "C" void kernel_launch(void* const* d_in, const int* in_sizes, int n_in,
                              void* d_out, int out_size) {
  const float* logits         = (const float*)d_in[0];
  const int*   targets        = (const int*)d_in[1];
  const int*   input_lengths  = (const int*)d_in[2];
  const int*   target_lengths = (const int*)d_in[3];
  (void)in_sizes; (void)n_in; (void)out_size;

  ctc_fused_kernel<<<B_, 288>>>(logits, targets, input_lengths, target_lengths,
                                (float*)d_out);
}